// round 3
// baseline (speedup 1.0000x reference)
#include <cuda_runtime.h>

// ---------------- constants ----------------
namespace {
constexpr int Bb = 16;      // batch
constexpr int Cc = 256;     // channels
constexpr int Nn = 4096;    // H*W
constexpr int NH = 8;       // heads
constexpr int HD = 32;      // head dim
constexpr int AG = 49;      // agent tokens
constexpr float SCALE = 0.17677669529663689f;  // 32^-0.5
}

// ---------------- scratch (device globals; no allocation allowed) ----------------
__device__ float g_q[Bb * Nn * Cc];
__device__ float g_k[Bb * Nn * Cc];
__device__ float g_v[Bb * Nn * Cc];
__device__ float g_o[Bb * Nn * Cc];            // attention out + dwconv, pre-proj
__device__ float g_agent[Bb * AG * Cc];
__device__ float g_agentv[Bb * NH * AG * HD];
__device__ float g_bias1[NH * AG * Nn];        // stage-1 bias [h][a][n]
__device__ float g_bias2[NH * Nn * AG];        // stage-2 bias [h][n][a]
__device__ float g_S[Bb * NH * AG * Nn];       // stage-1 scores
__device__ float g_m[Bb * NH * AG];
__device__ float g_l[Bb * NH * AG];

// ---------------- bilinear coeffs for 7 -> 64 resize (half-pixel centers, edge clamp) ----------------
__device__ __forceinline__ void lin7(int i, int& j0, int& j1, float& w) {
    float c = (i + 0.5f) * (7.0f / 64.0f) - 0.5f;
    float f = floorf(c);
    w = c - f;
    int j = (int)f;
    j0 = max(0, min(6, j));
    j1 = max(0, min(6, j + 1));
}

__device__ __forceinline__ float bil7(const float* img, int y0, int y1, float wy,
                                      int x0, int x1, float wx) {
    float v0 = img[y0 * 7 + x0] * (1.f - wx) + img[y0 * 7 + x1] * wx;
    float v1 = img[y1 * 7 + x0] * (1.f - wx) + img[y1 * 7 + x1] * wx;
    return v0 * (1.f - wy) + v1 * wy;
}

// ---------------- K1: position biases ----------------
__global__ void k_bias(const float* __restrict__ an, const float* __restrict__ na,
                       const float* __restrict__ ahb, const float* __restrict__ awb,
                       const float* __restrict__ hab, const float* __restrict__ wab) {
    int n = blockIdx.x * 256 + threadIdx.x;   // grid.x = 16
    int a = blockIdx.y, h = blockIdx.z;
    int y = n >> 6, x = n & 63;
    int y0, y1, x0, x1; float wy, wx;
    lin7(y, y0, y1, wy);
    lin7(x, x0, x1, wx);
    const float* i1 = an + (h * AG + a) * 49;
    const float* i2 = na + (h * AG + a) * 49;
    float v1 = bil7(i1, y0, y1, wy, x0, x1, wx);
    float v2 = bil7(i2, y0, y1, wy, x0, x1, wx);
    g_bias1[(h * AG + a) * Nn + n] = v1 + ahb[(h * AG + a) * 64 + y] + awb[(h * AG + a) * 64 + x];
    g_bias2[(h * Nn + n) * AG + a] = v2 + hab[(h * 64 + y) * AG + a] + wab[(h * 64 + x) * AG + a];
}

// ---------------- K2: fused q/k/v SGEMM ----------------
// C[b][n][j] = sum_k x[b][k][n] * W[j][k],  j in [0,768): q | k | v
__global__ __launch_bounds__(256) void k_qkv(const float* __restrict__ x,
                                             const float* __restrict__ Wq,
                                             const float* __restrict__ Wkv) {
    __shared__ __align__(16) float As[16][132];
    __shared__ __align__(16) float Bs[16][132];
    int b = blockIdx.z;
    int n0 = blockIdx.x * 128;
    int j0 = blockIdx.y * 128;
    int t = threadIdx.x;
    int tm = (t >> 4) << 3;
    int tn = (t & 15) << 3;
    float acc[8][8];
#pragma unroll
    for (int i = 0; i < 8; i++)
#pragma unroll
        for (int j = 0; j < 8; j++) acc[i][j] = 0.f;

    const float* xb = x + b * Cc * Nn;
    for (int k0 = 0; k0 < Cc; k0 += 16) {
#pragma unroll
        for (int i = 0; i < 8; i++) {
            int idx = t + i * 256;
            int kk = idx >> 7, mm = idx & 127;
            As[kk][mm] = xb[(k0 + kk) * Nn + n0 + mm];
        }
#pragma unroll
        for (int i = 0; i < 8; i++) {
            int idx = t + i * 256;
            int jj = idx >> 4, kk = idx & 15;
            int jg = j0 + jj;
            const float* Wrow = (jg < 256) ? (Wq + jg * Cc) : (Wkv + (jg - 256) * Cc);
            Bs[kk][jj] = Wrow[k0 + kk];
        }
        __syncthreads();
#pragma unroll
        for (int kk = 0; kk < 16; kk++) {
            float a0[8], b0[8];
            *(float4*)&a0[0] = *(const float4*)&As[kk][tm];
            *(float4*)&a0[4] = *(const float4*)&As[kk][tm + 4];
            *(float4*)&b0[0] = *(const float4*)&Bs[kk][tn];
            *(float4*)&b0[4] = *(const float4*)&Bs[kk][tn + 4];
#pragma unroll
            for (int i = 0; i < 8; i++)
#pragma unroll
                for (int j = 0; j < 8; j++) acc[i][j] += a0[i] * b0[j];
        }
        __syncthreads();
    }
#pragma unroll
    for (int i = 0; i < 8; i++) {
        int m = n0 + tm + i;
#pragma unroll
        for (int jq = 0; jq < 2; jq++) {
            int j = j0 + tn + jq * 4;
            float* dst; int jl;
            if (j < 256)      { dst = g_q; jl = j; }
            else if (j < 512) { dst = g_k; jl = j - 256; }
            else              { dst = g_v; jl = j - 512; }
            float4 v = make_float4(acc[i][jq * 4 + 0], acc[i][jq * 4 + 1],
                                   acc[i][jq * 4 + 2], acc[i][jq * 4 + 3]);
            *(float4*)&dst[(b * Nn + m) * Cc + jl] = v;
        }
    }
}

// ---------------- K3: adaptive avg pool q -> agent (all bins 10x10) ----------------
__global__ void k_pool() {
    int c = threadIdx.x;
    int a = blockIdx.x;   // 49
    int b = blockIdx.y;   // 16
    int p = a / 7, q = a % 7;
    int ys = (p * 64) / 7, ye = ((p + 1) * 64 + 6) / 7;
    int xs = (q * 64) / 7, xe = ((q + 1) * 64 + 6) / 7;
    float s = 0.f;
    for (int y = ys; y < ye; y++)
        for (int x = xs; x < xe; x++)
            s += g_q[(b * Nn + y * 64 + x) * Cc + c];
    g_agent[(b * AG + a) * Cc + c] = s * (1.0f / ((ye - ys) * (xe - xs)));
}

// ---------------- K4: stage-1 scores S[b,h,a,n] = scale*ah.kh + bias1 ----------------
__global__ __launch_bounds__(256) void k_s1() {
    __shared__ __align__(16) float ah_s[AG * HD];
    __shared__ __align__(16) float k_s[128][33];
    int t = threadIdx.x;
    int n0 = blockIdx.x * 128, h = blockIdx.y, b = blockIdx.z;
    for (int idx = t; idx < AG * HD; idx += 256) {
        int a = idx >> 5, d = idx & 31;
        ah_s[idx] = g_agent[(b * AG + a) * Cc + h * HD + d];
    }
#pragma unroll
    for (int i = 0; i < 16; i++) {
        int idx = t + i * 256;
        int nn = idx >> 5, d = idx & 31;
        k_s[nn][d] = g_k[(b * Nn + n0 + nn) * Cc + h * HD + d];
    }
    __syncthreads();
    int n_l = t & 127;
    int a0 = t >> 7;
    float kreg[32];
#pragma unroll
    for (int d = 0; d < 32; d++) kreg[d] = k_s[n_l][d];
    float* Srow = g_S + ((b * NH + h) * AG) * Nn;
    const float* brow = g_bias1 + (h * AG) * Nn;
    for (int a = a0; a < AG; a += 2) {
        float s = 0.f;
#pragma unroll
        for (int i = 0; i < 8; i++) {
            float4 w = *(const float4*)&ah_s[a * HD + i * 4];
            s += w.x * kreg[i * 4 + 0] + w.y * kreg[i * 4 + 1]
               + w.z * kreg[i * 4 + 2] + w.w * kreg[i * 4 + 3];
        }
        Srow[a * Nn + n0 + n_l] = s * SCALE + brow[a * Nn + n0 + n_l];
    }
}

// ---------------- K5: per-row max / sum-exp ----------------
__global__ void k_stats() {
    int a = blockIdx.x, h = blockIdx.y, b = blockIdx.z;
    const float* row = g_S + ((b * NH + h) * AG + a) * Nn;
    int t = threadIdx.x;
    __shared__ float red[256];
    float mx = -1e30f;
    for (int i = t; i < Nn; i += 256) mx = fmaxf(mx, row[i]);
    red[t] = mx;
    __syncthreads();
    for (int s = 128; s > 0; s >>= 1) {
        if (t < s) red[t] = fmaxf(red[t], red[t + s]);
        __syncthreads();
    }
    mx = red[0];
    __syncthreads();
    float sm = 0.f;
    for (int i = t; i < Nn; i += 256) sm += __expf(row[i] - mx);
    red[t] = sm;
    __syncthreads();
    for (int s = 128; s > 0; s >>= 1) {
        if (t < s) red[t] += red[t + s];
        __syncthreads();
    }
    if (t == 0) {
        int idx = (b * NH + h) * AG + a;
        g_m[idx] = mx;
        g_l[idx] = red[0];
    }
}

// ---------------- K6: agent_v = softmax(S) @ V, per (b,h) ----------------
__global__ __launch_bounds__(256) void k_av() {
    __shared__ __align__(16) float p_s[AG][68];
    __shared__ __align__(16) float v_s[HD][68];
    __shared__ float mx_s[AG], li_s[AG];
    int h = blockIdx.x, b = blockIdx.y;
    int t = threadIdx.x;
    int bh = b * NH + h;
    if (t < AG) {
        mx_s[t] = g_m[bh * AG + t];
        li_s[t] = 1.0f / g_l[bh * AG + t];
    }
    __syncthreads();
    int d2 = t & 15;
    int grp = t >> 4;
    float acc[4][2];
#pragma unroll
    for (int i = 0; i < 4; i++) { acc[i][0] = 0.f; acc[i][1] = 0.f; }
    const float* Sbase = g_S + bh * AG * Nn;
    const float* vbase = g_v + b * Nn * Cc + h * HD;
    for (int n0 = 0; n0 < Nn; n0 += 64) {
#pragma unroll
        for (int i = 0; i < 8; i++) {
            int idx = t + i * 256;
            int nn = idx >> 5, d = idx & 31;
            v_s[d][nn] = vbase[(n0 + nn) * Cc + d];
        }
        for (int idx = t; idx < AG * 64; idx += 256) {
            int a = idx >> 6, nn = idx & 63;
            float s = Sbase[a * Nn + n0 + nn];
            p_s[a][nn] = __expf(s - mx_s[a]) * li_s[a];
        }
        __syncthreads();
#pragma unroll
        for (int i = 0; i < 4; i++) {
            int a = grp + i * 16;
            if (a < AG) {
#pragma unroll
                for (int n4 = 0; n4 < 64; n4 += 4) {
                    float4 p4 = *(const float4*)&p_s[a][n4];
                    float4 va = *(const float4*)&v_s[d2][n4];
                    float4 vb = *(const float4*)&v_s[d2 + 16][n4];
                    acc[i][0] += p4.x * va.x + p4.y * va.y + p4.z * va.z + p4.w * va.w;
                    acc[i][1] += p4.x * vb.x + p4.y * vb.y + p4.z * vb.z + p4.w * vb.w;
                }
            }
        }
        __syncthreads();
    }
#pragma unroll
    for (int i = 0; i < 4; i++) {
        int a = grp + i * 16;
        if (a < AG) {
            g_agentv[(bh * AG + a) * HD + d2]      = acc[i][0];
            g_agentv[(bh * AG + a) * HD + d2 + 16] = acc[i][1];
        }
    }
}

// ---------------- K7: fused stage-2 (scores -> softmax(49) -> @agent_v) ----------------
__global__ __launch_bounds__(256) void k_st2() {
    __shared__ __align__(16) float ah_s[AG * HD];
    __shared__ __align__(16) float av_s[AG * HD];
    __shared__ __align__(16) float p_sm[AG][128];
    __shared__ float li_sm[128];
    int t = threadIdx.x;
    int n0 = blockIdx.x * 128, h = blockIdx.y, b = blockIdx.z;
    for (int idx = t; idx < AG * HD; idx += 256) {
        int a = idx >> 5, d = idx & 31;
        ah_s[idx] = g_agent[(b * AG + a) * Cc + h * HD + d];
        av_s[idx] = g_agentv[((b * NH + h) * AG + a) * HD + d];
    }
    __syncthreads();
    {   // phase 1: scores
        int n_l = t & 127, a0 = t >> 7;
        float4 q4[8];
        const float4* qp = (const float4*)(g_q + (b * Nn + n0 + n_l) * Cc + h * HD);
#pragma unroll
        for (int i = 0; i < 8; i++) q4[i] = qp[i];
        const float* b2 = g_bias2 + (h * Nn + n0 + n_l) * AG;
        for (int a = a0; a < AG; a += 2) {
            float s = 0.f;
#pragma unroll
            for (int i = 0; i < 8; i++) {
                float4 w = *(const float4*)&ah_s[a * HD + i * 4];
                s += q4[i].x * w.x + q4[i].y * w.y + q4[i].z * w.z + q4[i].w * w.w;
            }
            p_sm[a][n_l] = s * SCALE + b2[a];
        }
    }
    __syncthreads();
    if (t < 128) {   // phase 2: softmax over a (49)
        float mx = -1e30f;
        for (int a = 0; a < AG; a++) mx = fmaxf(mx, p_sm[a][t]);
        float sm = 0.f;
        for (int a = 0; a < AG; a++) {
            float e = __expf(p_sm[a][t] - mx);
            p_sm[a][t] = e;
            sm += e;
        }
        li_sm[t] = 1.0f / sm;
    }
    __syncthreads();
    {   // phase 3: out[n][d] = sum_a p[a][n]*av[a][d]
        int d = t & 31, grp = t >> 5;
        int nb = grp * 16;
        float acc[16];
#pragma unroll
        for (int i = 0; i < 16; i++) acc[i] = 0.f;
        for (int a = 0; a < AG; a++) {
            float av = av_s[a * HD + d];
#pragma unroll
            for (int i4 = 0; i4 < 4; i4++) {
                float4 p4 = *(const float4*)&p_sm[a][nb + i4 * 4];
                acc[i4 * 4 + 0] += p4.x * av;
                acc[i4 * 4 + 1] += p4.y * av;
                acc[i4 * 4 + 2] += p4.z * av;
                acc[i4 * 4 + 3] += p4.w * av;
            }
        }
#pragma unroll
        for (int i = 0; i < 16; i++) {
            int n = nb + i;
            g_o[(b * Nn + n0 + n) * Cc + h * HD + d] = acc[i] * li_sm[n];
        }
    }
}

// ---------------- K8: depthwise 3x3 conv on v, accumulate into g_o ----------------
__global__ void k_dw(const float* __restrict__ Wd, const float* __restrict__ bd) {
    int c = threadIdx.x;
    int n = blockIdx.x, b = blockIdx.y;
    int y = n >> 6, x = n & 63;
    float s = bd[c];
#pragma unroll
    for (int dy = -1; dy <= 1; dy++) {
        int yy = y + dy;
        if (yy < 0 || yy > 63) continue;
#pragma unroll
        for (int dx = -1; dx <= 1; dx++) {
            int xx = x + dx;
            if (xx < 0 || xx > 63) continue;
            s += g_v[(b * Nn + yy * 64 + xx) * Cc + c] * Wd[c * 9 + (dy + 1) * 3 + (dx + 1)];
        }
    }
    g_o[(b * Nn + n) * Cc + c] += s;
}

// ---------------- K9: proj SGEMM, writes transposed output [b][c][n] ----------------
__global__ __launch_bounds__(256) void k_proj(const float* __restrict__ Wp,
                                              const float* __restrict__ bp,
                                              float* __restrict__ out) {
    __shared__ __align__(16) float As[16][132];
    __shared__ __align__(16) float Bs[16][132];
    int b = blockIdx.z;
    int n0 = blockIdx.x * 128;
    int j0 = blockIdx.y * 128;
    int t = threadIdx.x;
    int tm = (t >> 4) << 3;
    int tn = (t & 15) << 3;
    float acc[8][8];
#pragma unroll
    for (int i = 0; i < 8; i++)
#pragma unroll
        for (int j = 0; j < 8; j++) acc[i][j] = 0.f;

    const float* Ab = g_o + b * Nn * Cc;
    for (int k0 = 0; k0 < Cc; k0 += 16) {
#pragma unroll
        for (int i = 0; i < 2; i++) {
            int idx4 = t + i * 256;
            int m = idx4 >> 2, k4 = idx4 & 3;
            float4 v = *(const float4*)&Ab[(n0 + m) * Cc + k0 + k4 * 4];
            As[k4 * 4 + 0][m] = v.x;
            As[k4 * 4 + 1][m] = v.y;
            As[k4 * 4 + 2][m] = v.z;
            As[k4 * 4 + 3][m] = v.w;
        }
#pragma unroll
        for (int i = 0; i < 8; i++) {
            int idx = t + i * 256;
            int jj = idx >> 4, kk = idx & 15;
            Bs[kk][jj] = Wp[(j0 + jj) * Cc + k0 + kk];
        }
        __syncthreads();
#pragma unroll
        for (int kk = 0; kk < 16; kk++) {
            float a0[8], b0[8];
            *(float4*)&a0[0] = *(const float4*)&As[kk][tm];
            *(float4*)&a0[4] = *(const float4*)&As[kk][tm + 4];
            *(float4*)&b0[0] = *(const float4*)&Bs[kk][tn];
            *(float4*)&b0[4] = *(const float4*)&Bs[kk][tn + 4];
#pragma unroll
            for (int i = 0; i < 8; i++)
#pragma unroll
                for (int j = 0; j < 8; j++) acc[i][j] += a0[i] * b0[j];
        }
        __syncthreads();
    }
#pragma unroll
    for (int jj = 0; jj < 8; jj++) {
        int j = j0 + tn + jj;
        float bb = bp[j];
        float4 v0 = make_float4(acc[0][jj] + bb, acc[1][jj] + bb, acc[2][jj] + bb, acc[3][jj] + bb);
        float4 v1 = make_float4(acc[4][jj] + bb, acc[5][jj] + bb, acc[6][jj] + bb, acc[7][jj] + bb);
        float* dst = out + (b * Cc + j) * Nn + n0 + tm;
        *(float4*)&dst[0] = v0;
        *(float4*)&dst[4] = v1;
    }
}

// ---------------- launch ----------------
extern "C" void kernel_launch(void* const* d_in, const int* in_sizes, int n_in,
                              void* d_out, int out_size) {
    const float* x     = (const float*)d_in[0];
    const float* Wq    = (const float*)d_in[1];
    const float* Wkv   = (const float*)d_in[2];
    const float* Wproj = (const float*)d_in[3];
    const float* bproj = (const float*)d_in[4];
    const float* Wdwc  = (const float*)d_in[5];
    const float* bdwc  = (const float*)d_in[6];
    const float* an    = (const float*)d_in[7];
    const float* na    = (const float*)d_in[8];
    const float* ahb   = (const float*)d_in[9];
    const float* awb   = (const float*)d_in[10];
    const float* hab   = (const float*)d_in[11];
    const float* wab   = (const float*)d_in[12];
    float* out = (float*)d_out;

    k_bias <<<dim3(Nn / 256, AG, NH), 256>>>(an, na, ahb, awb, hab, wab);
    k_qkv  <<<dim3(Nn / 128, 6, Bb), 256>>>(x, Wq, Wkv);
    k_pool <<<dim3(AG, Bb), 256>>>();
    k_s1   <<<dim3(Nn / 128, NH, Bb), 256>>>();
    k_stats<<<dim3(AG, NH, Bb), 256>>>();
    k_av   <<<dim3(NH, Bb), 256>>>();
    k_st2  <<<dim3(Nn / 128, NH, Bb), 256>>>();
    k_dw   <<<dim3(Nn, Bb), 256>>>(Wdwc, bdwc);
    k_proj <<<dim3(Nn / 128, Cc / 128, Bb), 256>>>(Wproj, bproj, out);
}

// round 4
// speedup vs baseline: 1.0007x; 1.0007x over previous
#include <cuda_runtime.h>

// ---------------- constants ----------------
namespace {
constexpr int Bb = 16;      // batch
constexpr int Cc = 256;     // channels
constexpr int Nn = 4096;    // H*W
constexpr int NH = 8;       // heads
constexpr int HD = 32;      // head dim
constexpr int AG = 49;      // agent tokens
constexpr float SCALE = 0.17677669529663689f;  // 32^-0.5
}

// ---------------- scratch (device globals; no allocation allowed) ----------------
__device__ float g_q[Bb * Nn * Cc];
__device__ float g_k[Bb * Nn * Cc];
__device__ float g_v[Bb * Nn * Cc];
__device__ float g_o[Bb * Nn * Cc];            // attention out + dwconv, pre-proj
__device__ float g_agent[Bb * AG * Cc];
__device__ float g_agentv[Bb * NH * AG * HD];
__device__ float g_bias1[NH * AG * Nn];        // stage-1 bias [h][a][n]
__device__ float g_bias2[NH * Nn * AG];        // stage-2 bias [h][n][a]
__device__ float g_S[Bb * NH * AG * Nn];       // stage-1 scores
__device__ float g_m[Bb * NH * AG];
__device__ float g_l[Bb * NH * AG];

// ---------------- bilinear coeffs for 7 -> 64 resize (half-pixel centers, edge clamp) ----------------
__device__ __forceinline__ void lin7(int i, int& j0, int& j1, float& w) {
    float c = (i + 0.5f) * (7.0f / 64.0f) - 0.5f;
    float f = floorf(c);
    w = c - f;
    int j = (int)f;
    j0 = max(0, min(6, j));
    j1 = max(0, min(6, j + 1));
}

__device__ __forceinline__ float bil7(const float* img, int y0, int y1, float wy,
                                      int x0, int x1, float wx) {
    float v0 = img[y0 * 7 + x0] * (1.f - wx) + img[y0 * 7 + x1] * wx;
    float v1 = img[y1 * 7 + x0] * (1.f - wx) + img[y1 * 7 + x1] * wx;
    return v0 * (1.f - wy) + v1 * wy;
}

// ---------------- K1: position biases ----------------
__global__ void k_bias(const float* __restrict__ an, const float* __restrict__ na,
                       const float* __restrict__ ahb, const float* __restrict__ awb,
                       const float* __restrict__ hab, const float* __restrict__ wab) {
    int n = blockIdx.x * 256 + threadIdx.x;   // grid.x = 16
    int a = blockIdx.y, h = blockIdx.z;
    int y = n >> 6, x = n & 63;
    int y0, y1, x0, x1; float wy, wx;
    lin7(y, y0, y1, wy);
    lin7(x, x0, x1, wx);
    const float* i1 = an + (h * AG + a) * 49;
    const float* i2 = na + (h * AG + a) * 49;
    float v1 = bil7(i1, y0, y1, wy, x0, x1, wx);
    float v2 = bil7(i2, y0, y1, wy, x0, x1, wx);
    g_bias1[(h * AG + a) * Nn + n] = v1 + ahb[(h * AG + a) * 64 + y] + awb[(h * AG + a) * 64 + x];
    g_bias2[(h * Nn + n) * AG + a] = v2 + hab[(h * 64 + y) * AG + a] + wab[(h * 64 + x) * AG + a];
}

// ---------------- K2: fused q/k/v SGEMM ----------------
// C[b][n][j] = sum_k x[b][k][n] * W[j][k],  j in [0,768): q | k | v
__global__ __launch_bounds__(256) void k_qkv(const float* __restrict__ x,
                                             const float* __restrict__ Wq,
                                             const float* __restrict__ Wkv) {
    __shared__ __align__(16) float As[16][132];
    __shared__ __align__(16) float Bs[16][132];
    int b = blockIdx.z;
    int n0 = blockIdx.x * 128;
    int j0 = blockIdx.y * 128;
    int t = threadIdx.x;
    int tm = (t >> 4) << 3;
    int tn = (t & 15) << 3;
    float acc[8][8];
#pragma unroll
    for (int i = 0; i < 8; i++)
#pragma unroll
        for (int j = 0; j < 8; j++) acc[i][j] = 0.f;

    const float* xb = x + b * Cc * Nn;
    for (int k0 = 0; k0 < Cc; k0 += 16) {
#pragma unroll
        for (int i = 0; i < 8; i++) {
            int idx = t + i * 256;
            int kk = idx >> 7, mm = idx & 127;
            As[kk][mm] = xb[(k0 + kk) * Nn + n0 + mm];
        }
#pragma unroll
        for (int i = 0; i < 8; i++) {
            int idx = t + i * 256;
            int jj = idx >> 4, kk = idx & 15;
            int jg = j0 + jj;
            const float* Wrow = (jg < 256) ? (Wq + jg * Cc) : (Wkv + (jg - 256) * Cc);
            Bs[kk][jj] = Wrow[k0 + kk];
        }
        __syncthreads();
#pragma unroll
        for (int kk = 0; kk < 16; kk++) {
            float a0[8], b0[8];
            *(float4*)&a0[0] = *(const float4*)&As[kk][tm];
            *(float4*)&a0[4] = *(const float4*)&As[kk][tm + 4];
            *(float4*)&b0[0] = *(const float4*)&Bs[kk][tn];
            *(float4*)&b0[4] = *(const float4*)&Bs[kk][tn + 4];
#pragma unroll
            for (int i = 0; i < 8; i++)
#pragma unroll
                for (int j = 0; j < 8; j++) acc[i][j] += a0[i] * b0[j];
        }
        __syncthreads();
    }
#pragma unroll
    for (int i = 0; i < 8; i++) {
        int m = n0 + tm + i;
#pragma unroll
        for (int jq = 0; jq < 2; jq++) {
            int j = j0 + tn + jq * 4;
            float* dst; int jl;
            if (j < 256)      { dst = g_q; jl = j; }
            else if (j < 512) { dst = g_k; jl = j - 256; }
            else              { dst = g_v; jl = j - 512; }
            float4 v = make_float4(acc[i][jq * 4 + 0], acc[i][jq * 4 + 1],
                                   acc[i][jq * 4 + 2], acc[i][jq * 4 + 3]);
            *(float4*)&dst[(b * Nn + m) * Cc + jl] = v;
        }
    }
}

// ---------------- K3: adaptive avg pool q -> agent (all bins 10x10) ----------------
__global__ void k_pool() {
    int c = threadIdx.x;
    int a = blockIdx.x;   // 49
    int b = blockIdx.y;   // 16
    int p = a / 7, q = a % 7;
    int ys = (p * 64) / 7, ye = ((p + 1) * 64 + 6) / 7;
    int xs = (q * 64) / 7, xe = ((q + 1) * 64 + 6) / 7;
    float s = 0.f;
    for (int y = ys; y < ye; y++)
        for (int x = xs; x < xe; x++)
            s += g_q[(b * Nn + y * 64 + x) * Cc + c];
    g_agent[(b * AG + a) * Cc + c] = s * (1.0f / ((ye - ys) * (xe - xs)));
}

// ---------------- K4: stage-1 scores S[b,h,a,n] = scale*ah.kh + bias1 ----------------
__global__ __launch_bounds__(256) void k_s1() {
    __shared__ __align__(16) float ah_s[AG * HD];
    __shared__ __align__(16) float k_s[128][33];
    int t = threadIdx.x;
    int n0 = blockIdx.x * 128, h = blockIdx.y, b = blockIdx.z;
    for (int idx = t; idx < AG * HD; idx += 256) {
        int a = idx >> 5, d = idx & 31;
        ah_s[idx] = g_agent[(b * AG + a) * Cc + h * HD + d];
    }
#pragma unroll
    for (int i = 0; i < 16; i++) {
        int idx = t + i * 256;
        int nn = idx >> 5, d = idx & 31;
        k_s[nn][d] = g_k[(b * Nn + n0 + nn) * Cc + h * HD + d];
    }
    __syncthreads();
    int n_l = t & 127;
    int a0 = t >> 7;
    float kreg[32];
#pragma unroll
    for (int d = 0; d < 32; d++) kreg[d] = k_s[n_l][d];
    float* Srow = g_S + ((b * NH + h) * AG) * Nn;
    const float* brow = g_bias1 + (h * AG) * Nn;
    for (int a = a0; a < AG; a += 2) {
        float s = 0.f;
#pragma unroll
        for (int i = 0; i < 8; i++) {
            float4 w = *(const float4*)&ah_s[a * HD + i * 4];
            s += w.x * kreg[i * 4 + 0] + w.y * kreg[i * 4 + 1]
               + w.z * kreg[i * 4 + 2] + w.w * kreg[i * 4 + 3];
        }
        Srow[a * Nn + n0 + n_l] = s * SCALE + brow[a * Nn + n0 + n_l];
    }
}

// ---------------- K5: per-row max / sum-exp ----------------
__global__ void k_stats() {
    int a = blockIdx.x, h = blockIdx.y, b = blockIdx.z;
    const float* row = g_S + ((b * NH + h) * AG + a) * Nn;
    int t = threadIdx.x;
    __shared__ float red[256];
    float mx = -1e30f;
    for (int i = t; i < Nn; i += 256) mx = fmaxf(mx, row[i]);
    red[t] = mx;
    __syncthreads();
    for (int s = 128; s > 0; s >>= 1) {
        if (t < s) red[t] = fmaxf(red[t], red[t + s]);
        __syncthreads();
    }
    mx = red[0];
    __syncthreads();
    float sm = 0.f;
    for (int i = t; i < Nn; i += 256) sm += __expf(row[i] - mx);
    red[t] = sm;
    __syncthreads();
    for (int s = 128; s > 0; s >>= 1) {
        if (t < s) red[t] += red[t + s];
        __syncthreads();
    }
    if (t == 0) {
        int idx = (b * NH + h) * AG + a;
        g_m[idx] = mx;
        g_l[idx] = red[0];
    }
}

// ---------------- K6: agent_v = softmax(S) @ V, per (b,h) ----------------
__global__ __launch_bounds__(256) void k_av() {
    __shared__ __align__(16) float p_s[AG][68];
    __shared__ __align__(16) float v_s[HD][68];
    __shared__ float mx_s[AG], li_s[AG];
    int h = blockIdx.x, b = blockIdx.y;
    int t = threadIdx.x;
    int bh = b * NH + h;
    if (t < AG) {
        mx_s[t] = g_m[bh * AG + t];
        li_s[t] = 1.0f / g_l[bh * AG + t];
    }
    __syncthreads();
    int d2 = t & 15;
    int grp = t >> 4;
    float acc[4][2];
#pragma unroll
    for (int i = 0; i < 4; i++) { acc[i][0] = 0.f; acc[i][1] = 0.f; }
    const float* Sbase = g_S + bh * AG * Nn;
    const float* vbase = g_v + b * Nn * Cc + h * HD;
    for (int n0 = 0; n0 < Nn; n0 += 64) {
#pragma unroll
        for (int i = 0; i < 8; i++) {
            int idx = t + i * 256;
            int nn = idx >> 5, d = idx & 31;
            v_s[d][nn] = vbase[(n0 + nn) * Cc + d];
        }
        for (int idx = t; idx < AG * 64; idx += 256) {
            int a = idx >> 6, nn = idx & 63;
            float s = Sbase[a * Nn + n0 + nn];
            p_s[a][nn] = __expf(s - mx_s[a]) * li_s[a];
        }
        __syncthreads();
#pragma unroll
        for (int i = 0; i < 4; i++) {
            int a = grp + i * 16;
            if (a < AG) {
#pragma unroll
                for (int n4 = 0; n4 < 64; n4 += 4) {
                    float4 p4 = *(const float4*)&p_s[a][n4];
                    float4 va = *(const float4*)&v_s[d2][n4];
                    float4 vb = *(const float4*)&v_s[d2 + 16][n4];
                    acc[i][0] += p4.x * va.x + p4.y * va.y + p4.z * va.z + p4.w * va.w;
                    acc[i][1] += p4.x * vb.x + p4.y * vb.y + p4.z * vb.z + p4.w * vb.w;
                }
            }
        }
        __syncthreads();
    }
#pragma unroll
    for (int i = 0; i < 4; i++) {
        int a = grp + i * 16;
        if (a < AG) {
            g_agentv[(bh * AG + a) * HD + d2]      = acc[i][0];
            g_agentv[(bh * AG + a) * HD + d2 + 16] = acc[i][1];
        }
    }
}

// ---------------- K7: fused stage-2 (scores -> softmax(49) -> @agent_v) ----------------
__global__ __launch_bounds__(256) void k_st2() {
    __shared__ __align__(16) float ah_s[AG * HD];
    __shared__ __align__(16) float av_s[AG * HD];
    __shared__ __align__(16) float p_sm[AG][128];
    __shared__ float li_sm[128];
    int t = threadIdx.x;
    int n0 = blockIdx.x * 128, h = blockIdx.y, b = blockIdx.z;
    for (int idx = t; idx < AG * HD; idx += 256) {
        int a = idx >> 5, d = idx & 31;
        ah_s[idx] = g_agent[(b * AG + a) * Cc + h * HD + d];
        av_s[idx] = g_agentv[((b * NH + h) * AG + a) * HD + d];
    }
    __syncthreads();
    {   // phase 1: scores
        int n_l = t & 127, a0 = t >> 7;
        float4 q4[8];
        const float4* qp = (const float4*)(g_q + (b * Nn + n0 + n_l) * Cc + h * HD);
#pragma unroll
        for (int i = 0; i < 8; i++) q4[i] = qp[i];
        const float* b2 = g_bias2 + (h * Nn + n0 + n_l) * AG;
        for (int a = a0; a < AG; a += 2) {
            float s = 0.f;
#pragma unroll
            for (int i = 0; i < 8; i++) {
                float4 w = *(const float4*)&ah_s[a * HD + i * 4];
                s += q4[i].x * w.x + q4[i].y * w.y + q4[i].z * w.z + q4[i].w * w.w;
            }
            p_sm[a][n_l] = s * SCALE + b2[a];
        }
    }
    __syncthreads();
    if (t < 128) {   // phase 2: softmax over a (49)
        float mx = -1e30f;
        for (int a = 0; a < AG; a++) mx = fmaxf(mx, p_sm[a][t]);
        float sm = 0.f;
        for (int a = 0; a < AG; a++) {
            float e = __expf(p_sm[a][t] - mx);
            p_sm[a][t] = e;
            sm += e;
        }
        li_sm[t] = 1.0f / sm;
    }
    __syncthreads();
    {   // phase 3: out[n][d] = sum_a p[a][n]*av[a][d]
        int d = t & 31, grp = t >> 5;
        int nb = grp * 16;
        float acc[16];
#pragma unroll
        for (int i = 0; i < 16; i++) acc[i] = 0.f;
        for (int a = 0; a < AG; a++) {
            float av = av_s[a * HD + d];
#pragma unroll
            for (int i4 = 0; i4 < 4; i4++) {
                float4 p4 = *(const float4*)&p_sm[a][nb + i4 * 4];
                acc[i4 * 4 + 0] += p4.x * av;
                acc[i4 * 4 + 1] += p4.y * av;
                acc[i4 * 4 + 2] += p4.z * av;
                acc[i4 * 4 + 3] += p4.w * av;
            }
        }
#pragma unroll
        for (int i = 0; i < 16; i++) {
            int n = nb + i;
            g_o[(b * Nn + n0 + n) * Cc + h * HD + d] = acc[i] * li_sm[n];
        }
    }
}

// ---------------- K8: depthwise 3x3 conv on v, accumulate into g_o ----------------
__global__ void k_dw(const float* __restrict__ Wd, const float* __restrict__ bd) {
    int c = threadIdx.x;
    int n = blockIdx.x, b = blockIdx.y;
    int y = n >> 6, x = n & 63;
    float s = bd[c];
#pragma unroll
    for (int dy = -1; dy <= 1; dy++) {
        int yy = y + dy;
        if (yy < 0 || yy > 63) continue;
#pragma unroll
        for (int dx = -1; dx <= 1; dx++) {
            int xx = x + dx;
            if (xx < 0 || xx > 63) continue;
            s += g_v[(b * Nn + yy * 64 + xx) * Cc + c] * Wd[c * 9 + (dy + 1) * 3 + (dx + 1)];
        }
    }
    g_o[(b * Nn + n) * Cc + c] += s;
}

// ---------------- K9: proj SGEMM, writes transposed output [b][c][n] ----------------
__global__ __launch_bounds__(256) void k_proj(const float* __restrict__ Wp,
                                              const float* __restrict__ bp,
                                              float* __restrict__ out) {
    __shared__ __align__(16) float As[16][132];
    __shared__ __align__(16) float Bs[16][132];
    int b = blockIdx.z;
    int n0 = blockIdx.x * 128;
    int j0 = blockIdx.y * 128;
    int t = threadIdx.x;
    int tm = (t >> 4) << 3;
    int tn = (t & 15) << 3;
    float acc[8][8];
#pragma unroll
    for (int i = 0; i < 8; i++)
#pragma unroll
        for (int j = 0; j < 8; j++) acc[i][j] = 0.f;

    const float* Ab = g_o + b * Nn * Cc;
    for (int k0 = 0; k0 < Cc; k0 += 16) {
#pragma unroll
        for (int i = 0; i < 2; i++) {
            int idx4 = t + i * 256;
            int m = idx4 >> 2, k4 = idx4 & 3;
            float4 v = *(const float4*)&Ab[(n0 + m) * Cc + k0 + k4 * 4];
            As[k4 * 4 + 0][m] = v.x;
            As[k4 * 4 + 1][m] = v.y;
            As[k4 * 4 + 2][m] = v.z;
            As[k4 * 4 + 3][m] = v.w;
        }
#pragma unroll
        for (int i = 0; i < 8; i++) {
            int idx = t + i * 256;
            int jj = idx >> 4, kk = idx & 15;
            Bs[kk][jj] = Wp[(j0 + jj) * Cc + k0 + kk];
        }
        __syncthreads();
#pragma unroll
        for (int kk = 0; kk < 16; kk++) {
            float a0[8], b0[8];
            *(float4*)&a0[0] = *(const float4*)&As[kk][tm];
            *(float4*)&a0[4] = *(const float4*)&As[kk][tm + 4];
            *(float4*)&b0[0] = *(const float4*)&Bs[kk][tn];
            *(float4*)&b0[4] = *(const float4*)&Bs[kk][tn + 4];
#pragma unroll
            for (int i = 0; i < 8; i++)
#pragma unroll
                for (int j = 0; j < 8; j++) acc[i][j] += a0[i] * b0[j];
        }
        __syncthreads();
    }
#pragma unroll
    for (int jj = 0; jj < 8; jj++) {
        int j = j0 + tn + jj;
        float bb = bp[j];
        float4 v0 = make_float4(acc[0][jj] + bb, acc[1][jj] + bb, acc[2][jj] + bb, acc[3][jj] + bb);
        float4 v1 = make_float4(acc[4][jj] + bb, acc[5][jj] + bb, acc[6][jj] + bb, acc[7][jj] + bb);
        float* dst = out + (b * Cc + j) * Nn + n0 + tm;
        *(float4*)&dst[0] = v0;
        *(float4*)&dst[4] = v1;
    }
}

// ---------------- launch ----------------
extern "C" void kernel_launch(void* const* d_in, const int* in_sizes, int n_in,
                              void* d_out, int out_size) {
    const float* x     = (const float*)d_in[0];
    const float* Wq    = (const float*)d_in[1];
    const float* Wkv   = (const float*)d_in[2];
    const float* Wproj = (const float*)d_in[3];
    const float* bproj = (const float*)d_in[4];
    const float* Wdwc  = (const float*)d_in[5];
    const float* bdwc  = (const float*)d_in[6];
    const float* an    = (const float*)d_in[7];
    const float* na    = (const float*)d_in[8];
    const float* ahb   = (const float*)d_in[9];
    const float* awb   = (const float*)d_in[10];
    const float* hab   = (const float*)d_in[11];
    const float* wab   = (const float*)d_in[12];
    float* out = (float*)d_out;

    k_bias <<<dim3(Nn / 256, AG, NH), 256>>>(an, na, ahb, awb, hab, wab);
    k_qkv  <<<dim3(Nn / 128, 6, Bb), 256>>>(x, Wq, Wkv);
    k_pool <<<dim3(AG, Bb), 256>>>();
    k_s1   <<<dim3(Nn / 128, NH, Bb), 256>>>();
    k_stats<<<dim3(AG, NH, Bb), 256>>>();
    k_av   <<<dim3(NH, Bb), 256>>>();
    k_st2  <<<dim3(Nn / 128, NH, Bb), 256>>>();
    k_dw   <<<dim3(Nn, Bb), 256>>>(Wdwc, bdwc);
    k_proj <<<dim3(Nn / 128, Cc / 128, Bb), 256>>>(Wproj, bproj, out);
}

// round 5
// speedup vs baseline: 1.0071x; 1.0064x over previous
#include <cuda_runtime.h>

// ---------------- constants ----------------
namespace {
constexpr int Bb = 16;      // batch
constexpr int Cc = 256;     // channels
constexpr int Nn = 4096;    // H*W
constexpr int NH = 8;       // heads
constexpr int HD = 32;      // head dim
constexpr int AG = 49;      // agent tokens
constexpr float SCALE = 0.17677669529663689f;  // 32^-0.5
}

// ---------------- scratch (device globals; no allocation allowed) ----------------
__device__ float g_q[Bb * Nn * Cc];
__device__ float g_k[Bb * Nn * Cc];
__device__ float g_v[Bb * Nn * Cc];
__device__ float g_o[Bb * Nn * Cc];            // attention out + dwconv, pre-proj
__device__ float g_agent[Bb * AG * Cc];
__device__ float g_agentv[Bb * NH * AG * HD];
__device__ float g_bias1[NH * AG * Nn];        // stage-1 bias [h][a][n]
__device__ float g_bias2[NH * Nn * AG];        // stage-2 bias [h][n][a]
__device__ float g_S[Bb * NH * AG * Nn];       // stage-1 scores
__device__ float g_m[Bb * NH * AG];
__device__ float g_l[Bb * NH * AG];

// ---------------- bilinear coeffs for 7 -> 64 resize (half-pixel centers, edge clamp) ----------------
__device__ __forceinline__ void lin7(int i, int& j0, int& j1, float& w) {
    float c = (i + 0.5f) * (7.0f / 64.0f) - 0.5f;
    float f = floorf(c);
    w = c - f;
    int j = (int)f;
    j0 = max(0, min(6, j));
    j1 = max(0, min(6, j + 1));
}

__device__ __forceinline__ float bil7(const float* img, int y0, int y1, float wy,
                                      int x0, int x1, float wx) {
    float v0 = img[y0 * 7 + x0] * (1.f - wx) + img[y0 * 7 + x1] * wx;
    float v1 = img[y1 * 7 + x0] * (1.f - wx) + img[y1 * 7 + x1] * wx;
    return v0 * (1.f - wy) + v1 * wy;
}

// ---------------- K1: position biases ----------------
__global__ void k_bias(const float* __restrict__ an, const float* __restrict__ na,
                       const float* __restrict__ ahb, const float* __restrict__ awb,
                       const float* __restrict__ hab, const float* __restrict__ wab) {
    int n = blockIdx.x * 256 + threadIdx.x;   // grid.x = 16
    int a = blockIdx.y, h = blockIdx.z;
    int y = n >> 6, x = n & 63;
    int y0, y1, x0, x1; float wy, wx;
    lin7(y, y0, y1, wy);
    lin7(x, x0, x1, wx);
    const float* i1 = an + (h * AG + a) * 49;
    const float* i2 = na + (h * AG + a) * 49;
    float v1 = bil7(i1, y0, y1, wy, x0, x1, wx);
    float v2 = bil7(i2, y0, y1, wy, x0, x1, wx);
    g_bias1[(h * AG + a) * Nn + n] = v1 + ahb[(h * AG + a) * 64 + y] + awb[(h * AG + a) * 64 + x];
    g_bias2[(h * Nn + n) * AG + a] = v2 + hab[(h * 64 + y) * AG + a] + wab[(h * 64 + x) * AG + a];
}

// ---------------- K2: fused q/k/v SGEMM ----------------
// C[b][n][j] = sum_k x[b][k][n] * W[j][k],  j in [0,768): q | k | v
__global__ __launch_bounds__(256) void k_qkv(const float* __restrict__ x,
                                             const float* __restrict__ Wq,
                                             const float* __restrict__ Wkv) {
    __shared__ __align__(16) float As[16][132];
    __shared__ __align__(16) float Bs[16][132];
    int b = blockIdx.z;
    int n0 = blockIdx.x * 128;
    int j0 = blockIdx.y * 128;
    int t = threadIdx.x;
    int tm = (t >> 4) << 3;
    int tn = (t & 15) << 3;
    float acc[8][8];
#pragma unroll
    for (int i = 0; i < 8; i++)
#pragma unroll
        for (int j = 0; j < 8; j++) acc[i][j] = 0.f;

    const float* xb = x + b * Cc * Nn;
    for (int k0 = 0; k0 < Cc; k0 += 16) {
#pragma unroll
        for (int i = 0; i < 8; i++) {
            int idx = t + i * 256;
            int kk = idx >> 7, mm = idx & 127;
            As[kk][mm] = xb[(k0 + kk) * Nn + n0 + mm];
        }
#pragma unroll
        for (int i = 0; i < 8; i++) {
            int idx = t + i * 256;
            int jj = idx >> 4, kk = idx & 15;
            int jg = j0 + jj;
            const float* Wrow = (jg < 256) ? (Wq + jg * Cc) : (Wkv + (jg - 256) * Cc);
            Bs[kk][jj] = Wrow[k0 + kk];
        }
        __syncthreads();
#pragma unroll
        for (int kk = 0; kk < 16; kk++) {
            float a0[8], b0[8];
            *(float4*)&a0[0] = *(const float4*)&As[kk][tm];
            *(float4*)&a0[4] = *(const float4*)&As[kk][tm + 4];
            *(float4*)&b0[0] = *(const float4*)&Bs[kk][tn];
            *(float4*)&b0[4] = *(const float4*)&Bs[kk][tn + 4];
#pragma unroll
            for (int i = 0; i < 8; i++)
#pragma unroll
                for (int j = 0; j < 8; j++) acc[i][j] += a0[i] * b0[j];
        }
        __syncthreads();
    }
#pragma unroll
    for (int i = 0; i < 8; i++) {
        int m = n0 + tm + i;
#pragma unroll
        for (int jq = 0; jq < 2; jq++) {
            int j = j0 + tn + jq * 4;
            float* dst; int jl;
            if (j < 256)      { dst = g_q; jl = j; }
            else if (j < 512) { dst = g_k; jl = j - 256; }
            else              { dst = g_v; jl = j - 512; }
            float4 v = make_float4(acc[i][jq * 4 + 0], acc[i][jq * 4 + 1],
                                   acc[i][jq * 4 + 2], acc[i][jq * 4 + 3]);
            *(float4*)&dst[(b * Nn + m) * Cc + jl] = v;
        }
    }
}

// ---------------- K3: adaptive avg pool q -> agent (all bins 10x10) ----------------
__global__ void k_pool() {
    int c = threadIdx.x;
    int a = blockIdx.x;   // 49
    int b = blockIdx.y;   // 16
    int p = a / 7, q = a % 7;
    int ys = (p * 64) / 7, ye = ((p + 1) * 64 + 6) / 7;
    int xs = (q * 64) / 7, xe = ((q + 1) * 64 + 6) / 7;
    float s = 0.f;
    for (int y = ys; y < ye; y++)
        for (int x = xs; x < xe; x++)
            s += g_q[(b * Nn + y * 64 + x) * Cc + c];
    g_agent[(b * AG + a) * Cc + c] = s * (1.0f / ((ye - ys) * (xe - xs)));
}

// ---------------- K4: stage-1 scores S[b,h,a,n] = scale*ah.kh + bias1 ----------------
__global__ __launch_bounds__(256) void k_s1() {
    __shared__ __align__(16) float ah_s[AG * HD];
    __shared__ __align__(16) float k_s[128][33];
    int t = threadIdx.x;
    int n0 = blockIdx.x * 128, h = blockIdx.y, b = blockIdx.z;
    for (int idx = t; idx < AG * HD; idx += 256) {
        int a = idx >> 5, d = idx & 31;
        ah_s[idx] = g_agent[(b * AG + a) * Cc + h * HD + d];
    }
#pragma unroll
    for (int i = 0; i < 16; i++) {
        int idx = t + i * 256;
        int nn = idx >> 5, d = idx & 31;
        k_s[nn][d] = g_k[(b * Nn + n0 + nn) * Cc + h * HD + d];
    }
    __syncthreads();
    int n_l = t & 127;
    int a0 = t >> 7;
    float kreg[32];
#pragma unroll
    for (int d = 0; d < 32; d++) kreg[d] = k_s[n_l][d];
    float* Srow = g_S + ((b * NH + h) * AG) * Nn;
    const float* brow = g_bias1 + (h * AG) * Nn;
    for (int a = a0; a < AG; a += 2) {
        float s = 0.f;
#pragma unroll
        for (int i = 0; i < 8; i++) {
            float4 w = *(const float4*)&ah_s[a * HD + i * 4];
            s += w.x * kreg[i * 4 + 0] + w.y * kreg[i * 4 + 1]
               + w.z * kreg[i * 4 + 2] + w.w * kreg[i * 4 + 3];
        }
        Srow[a * Nn + n0 + n_l] = s * SCALE + brow[a * Nn + n0 + n_l];
    }
}

// ---------------- K5: per-row max / sum-exp ----------------
__global__ void k_stats() {
    int a = blockIdx.x, h = blockIdx.y, b = blockIdx.z;
    const float* row = g_S + ((b * NH + h) * AG + a) * Nn;
    int t = threadIdx.x;
    __shared__ float red[256];
    float mx = -1e30f;
    for (int i = t; i < Nn; i += 256) mx = fmaxf(mx, row[i]);
    red[t] = mx;
    __syncthreads();
    for (int s = 128; s > 0; s >>= 1) {
        if (t < s) red[t] = fmaxf(red[t], red[t + s]);
        __syncthreads();
    }
    mx = red[0];
    __syncthreads();
    float sm = 0.f;
    for (int i = t; i < Nn; i += 256) sm += __expf(row[i] - mx);
    red[t] = sm;
    __syncthreads();
    for (int s = 128; s > 0; s >>= 1) {
        if (t < s) red[t] += red[t + s];
        __syncthreads();
    }
    if (t == 0) {
        int idx = (b * NH + h) * AG + a;
        g_m[idx] = mx;
        g_l[idx] = red[0];
    }
}

// ---------------- K6: agent_v = softmax(S) @ V, per (b,h) ----------------
__global__ __launch_bounds__(256) void k_av() {
    __shared__ __align__(16) float p_s[AG][68];
    __shared__ __align__(16) float v_s[HD][68];
    __shared__ float mx_s[AG], li_s[AG];
    int h = blockIdx.x, b = blockIdx.y;
    int t = threadIdx.x;
    int bh = b * NH + h;
    if (t < AG) {
        mx_s[t] = g_m[bh * AG + t];
        li_s[t] = 1.0f / g_l[bh * AG + t];
    }
    __syncthreads();
    int d2 = t & 15;
    int grp = t >> 4;
    float acc[4][2];
#pragma unroll
    for (int i = 0; i < 4; i++) { acc[i][0] = 0.f; acc[i][1] = 0.f; }
    const float* Sbase = g_S + bh * AG * Nn;
    const float* vbase = g_v + b * Nn * Cc + h * HD;
    for (int n0 = 0; n0 < Nn; n0 += 64) {
#pragma unroll
        for (int i = 0; i < 8; i++) {
            int idx = t + i * 256;
            int nn = idx >> 5, d = idx & 31;
            v_s[d][nn] = vbase[(n0 + nn) * Cc + d];
        }
        for (int idx = t; idx < AG * 64; idx += 256) {
            int a = idx >> 6, nn = idx & 63;
            float s = Sbase[a * Nn + n0 + nn];
            p_s[a][nn] = __expf(s - mx_s[a]) * li_s[a];
        }
        __syncthreads();
#pragma unroll
        for (int i = 0; i < 4; i++) {
            int a = grp + i * 16;
            if (a < AG) {
#pragma unroll
                for (int n4 = 0; n4 < 64; n4 += 4) {
                    float4 p4 = *(const float4*)&p_s[a][n4];
                    float4 va = *(const float4*)&v_s[d2][n4];
                    float4 vb = *(const float4*)&v_s[d2 + 16][n4];
                    acc[i][0] += p4.x * va.x + p4.y * va.y + p4.z * va.z + p4.w * va.w;
                    acc[i][1] += p4.x * vb.x + p4.y * vb.y + p4.z * vb.z + p4.w * vb.w;
                }
            }
        }
        __syncthreads();
    }
#pragma unroll
    for (int i = 0; i < 4; i++) {
        int a = grp + i * 16;
        if (a < AG) {
            g_agentv[(bh * AG + a) * HD + d2]      = acc[i][0];
            g_agentv[(bh * AG + a) * HD + d2 + 16] = acc[i][1];
        }
    }
}

// ---------------- K7: fused stage-2 (scores -> softmax(49) -> @agent_v) ----------------
__global__ __launch_bounds__(256) void k_st2() {
    __shared__ __align__(16) float ah_s[AG * HD];
    __shared__ __align__(16) float av_s[AG * HD];
    __shared__ __align__(16) float p_sm[AG][128];
    __shared__ float li_sm[128];
    int t = threadIdx.x;
    int n0 = blockIdx.x * 128, h = blockIdx.y, b = blockIdx.z;
    for (int idx = t; idx < AG * HD; idx += 256) {
        int a = idx >> 5, d = idx & 31;
        ah_s[idx] = g_agent[(b * AG + a) * Cc + h * HD + d];
        av_s[idx] = g_agentv[((b * NH + h) * AG + a) * HD + d];
    }
    __syncthreads();
    {   // phase 1: scores
        int n_l = t & 127, a0 = t >> 7;
        float4 q4[8];
        const float4* qp = (const float4*)(g_q + (b * Nn + n0 + n_l) * Cc + h * HD);
#pragma unroll
        for (int i = 0; i < 8; i++) q4[i] = qp[i];
        const float* b2 = g_bias2 + (h * Nn + n0 + n_l) * AG;
        for (int a = a0; a < AG; a += 2) {
            float s = 0.f;
#pragma unroll
            for (int i = 0; i < 8; i++) {
                float4 w = *(const float4*)&ah_s[a * HD + i * 4];
                s += q4[i].x * w.x + q4[i].y * w.y + q4[i].z * w.z + q4[i].w * w.w;
            }
            p_sm[a][n_l] = s * SCALE + b2[a];
        }
    }
    __syncthreads();
    if (t < 128) {   // phase 2: softmax over a (49)
        float mx = -1e30f;
        for (int a = 0; a < AG; a++) mx = fmaxf(mx, p_sm[a][t]);
        float sm = 0.f;
        for (int a = 0; a < AG; a++) {
            float e = __expf(p_sm[a][t] - mx);
            p_sm[a][t] = e;
            sm += e;
        }
        li_sm[t] = 1.0f / sm;
    }
    __syncthreads();
    {   // phase 3: out[n][d] = sum_a p[a][n]*av[a][d]
        int d = t & 31, grp = t >> 5;
        int nb = grp * 16;
        float acc[16];
#pragma unroll
        for (int i = 0; i < 16; i++) acc[i] = 0.f;
        for (int a = 0; a < AG; a++) {
            float av = av_s[a * HD + d];
#pragma unroll
            for (int i4 = 0; i4 < 4; i4++) {
                float4 p4 = *(const float4*)&p_sm[a][nb + i4 * 4];
                acc[i4 * 4 + 0] += p4.x * av;
                acc[i4 * 4 + 1] += p4.y * av;
                acc[i4 * 4 + 2] += p4.z * av;
                acc[i4 * 4 + 3] += p4.w * av;
            }
        }
#pragma unroll
        for (int i = 0; i < 16; i++) {
            int n = nb + i;
            g_o[(b * Nn + n0 + n) * Cc + h * HD + d] = acc[i] * li_sm[n];
        }
    }
}

// ---------------- K8: depthwise 3x3 conv on v, accumulate into g_o ----------------
__global__ void k_dw(const float* __restrict__ Wd, const float* __restrict__ bd) {
    int c = threadIdx.x;
    int n = blockIdx.x, b = blockIdx.y;
    int y = n >> 6, x = n & 63;
    float s = bd[c];
#pragma unroll
    for (int dy = -1; dy <= 1; dy++) {
        int yy = y + dy;
        if (yy < 0 || yy > 63) continue;
#pragma unroll
        for (int dx = -1; dx <= 1; dx++) {
            int xx = x + dx;
            if (xx < 0 || xx > 63) continue;
            s += g_v[(b * Nn + yy * 64 + xx) * Cc + c] * Wd[c * 9 + (dy + 1) * 3 + (dx + 1)];
        }
    }
    g_o[(b * Nn + n) * Cc + c] += s;
}

// ---------------- K9: proj SGEMM, writes transposed output [b][c][n] ----------------
__global__ __launch_bounds__(256) void k_proj(const float* __restrict__ Wp,
                                              const float* __restrict__ bp,
                                              float* __restrict__ out) {
    __shared__ __align__(16) float As[16][132];
    __shared__ __align__(16) float Bs[16][132];
    int b = blockIdx.z;
    int n0 = blockIdx.x * 128;
    int j0 = blockIdx.y * 128;
    int t = threadIdx.x;
    int tm = (t >> 4) << 3;
    int tn = (t & 15) << 3;
    float acc[8][8];
#pragma unroll
    for (int i = 0; i < 8; i++)
#pragma unroll
        for (int j = 0; j < 8; j++) acc[i][j] = 0.f;

    const float* Ab = g_o + b * Nn * Cc;
    for (int k0 = 0; k0 < Cc; k0 += 16) {
#pragma unroll
        for (int i = 0; i < 2; i++) {
            int idx4 = t + i * 256;
            int m = idx4 >> 2, k4 = idx4 & 3;
            float4 v = *(const float4*)&Ab[(n0 + m) * Cc + k0 + k4 * 4];
            As[k4 * 4 + 0][m] = v.x;
            As[k4 * 4 + 1][m] = v.y;
            As[k4 * 4 + 2][m] = v.z;
            As[k4 * 4 + 3][m] = v.w;
        }
#pragma unroll
        for (int i = 0; i < 8; i++) {
            int idx = t + i * 256;
            int jj = idx >> 4, kk = idx & 15;
            Bs[kk][jj] = Wp[(j0 + jj) * Cc + k0 + kk];
        }
        __syncthreads();
#pragma unroll
        for (int kk = 0; kk < 16; kk++) {
            float a0[8], b0[8];
            *(float4*)&a0[0] = *(const float4*)&As[kk][tm];
            *(float4*)&a0[4] = *(const float4*)&As[kk][tm + 4];
            *(float4*)&b0[0] = *(const float4*)&Bs[kk][tn];
            *(float4*)&b0[4] = *(const float4*)&Bs[kk][tn + 4];
#pragma unroll
            for (int i = 0; i < 8; i++)
#pragma unroll
                for (int j = 0; j < 8; j++) acc[i][j] += a0[i] * b0[j];
        }
        __syncthreads();
    }
#pragma unroll
    for (int jj = 0; jj < 8; jj++) {
        int j = j0 + tn + jj;
        float bb = bp[j];
        float4 v0 = make_float4(acc[0][jj] + bb, acc[1][jj] + bb, acc[2][jj] + bb, acc[3][jj] + bb);
        float4 v1 = make_float4(acc[4][jj] + bb, acc[5][jj] + bb, acc[6][jj] + bb, acc[7][jj] + bb);
        float* dst = out + (b * Cc + j) * Nn + n0 + tm;
        *(float4*)&dst[0] = v0;
        *(float4*)&dst[4] = v1;
    }
}

// ---------------- launch ----------------
extern "C" void kernel_launch(void* const* d_in, const int* in_sizes, int n_in,
                              void* d_out, int out_size) {
    const float* x     = (const float*)d_in[0];
    const float* Wq    = (const float*)d_in[1];
    const float* Wkv   = (const float*)d_in[2];
    const float* Wproj = (const float*)d_in[3];
    const float* bproj = (const float*)d_in[4];
    const float* Wdwc  = (const float*)d_in[5];
    const float* bdwc  = (const float*)d_in[6];
    const float* an    = (const float*)d_in[7];
    const float* na    = (const float*)d_in[8];
    const float* ahb   = (const float*)d_in[9];
    const float* awb   = (const float*)d_in[10];
    const float* hab   = (const float*)d_in[11];
    const float* wab   = (const float*)d_in[12];
    float* out = (float*)d_out;

    k_bias <<<dim3(Nn / 256, AG, NH), 256>>>(an, na, ahb, awb, hab, wab);
    k_qkv  <<<dim3(Nn / 128, 6, Bb), 256>>>(x, Wq, Wkv);
    k_pool <<<dim3(AG, Bb), 256>>>();
    k_s1   <<<dim3(Nn / 128, NH, Bb), 256>>>();
    k_stats<<<dim3(AG, NH, Bb), 256>>>();
    k_av   <<<dim3(NH, Bb), 256>>>();
    k_st2  <<<dim3(Nn / 128, NH, Bb), 256>>>();
    k_dw   <<<dim3(Nn, Bb), 256>>>(Wdwc, bdwc);
    k_proj <<<dim3(Nn / 128, Cc / 128, Bb), 256>>>(Wproj, bproj, out);
}

// round 7
// speedup vs baseline: 1.4715x; 1.4610x over previous
#include <cuda_runtime.h>
#include <cuda_bf16.h>
#include <cstdint>

// ---------------- constants ----------------
namespace {
constexpr int Bb = 16;      // batch
constexpr int Cc = 256;     // channels
constexpr int Nn = 4096;    // H*W
constexpr int NH = 8;       // heads
constexpr int HD = 32;      // head dim
constexpr int AG = 49;      // agent tokens
constexpr float SCALE = 0.17677669529663689f;  // 32^-0.5
constexpr int AP = 264;                         // smem pitch (bf16 elems), conflict-free ldmatrix
constexpr unsigned A_BYTES = 128 * AP * 2;      // 67584
constexpr unsigned B_BYTES = 64 * AP * 2;       // 33792
constexpr unsigned SMEM_DYN = 2 * A_BYTES + 2 * B_BYTES;  // 202752
}

// ---------------- scratch (device globals; no allocation allowed) ----------------
__device__ float g_q[Bb * Nn * Cc];
__device__ float g_k[Bb * Nn * Cc];
__device__ float g_v[Bb * Nn * Cc];
__device__ float g_o[Bb * Nn * Cc];            // attention out + dwconv, pre-proj
__device__ float g_agent[Bb * AG * Cc];
__device__ float g_agentv[Bb * NH * AG * HD];
__device__ float g_bias1[NH * AG * Nn];        // stage-1 bias [h][a][n]
__device__ float g_bias2[NH * Nn * AG];        // stage-2 bias [h][n][a]
__device__ float g_S[Bb * NH * AG * Nn];       // stage-1 scores
__device__ float g_m[Bb * NH * AG];
__device__ float g_l[Bb * NH * AG];

// bf16 hi/lo split operands for tensor-core GEMMs
__device__ __nv_bfloat16 g_xh[Bb * Nn * Cc];   // xt row-major [b][n][c]
__device__ __nv_bfloat16 g_xl[Bb * Nn * Cc];
__device__ __nv_bfloat16 g_oh[Bb * Nn * Cc];
__device__ __nv_bfloat16 g_ol[Bb * Nn * Cc];
__device__ __nv_bfloat16 g_wh[768 * Cc];       // qkv weights combined [q|k|v]
__device__ __nv_bfloat16 g_wl[768 * Cc];
__device__ __nv_bfloat16 g_pwh[Cc * Cc];       // proj weights
__device__ __nv_bfloat16 g_pwl[Cc * Cc];

// ---------------- PTX helpers (baseline sm_80+ features only) ----------------
__device__ __forceinline__ uint32_t smem_u32(const void* p) {
    uint32_t a;
    asm("{ .reg .u64 t; cvta.to.shared.u64 t, %1; cvt.u32.u64 %0, t; }" : "=r"(a) : "l"(p));
    return a;
}
__device__ __forceinline__ void ldm_x4(uint32_t* r, uint32_t addr) {
    asm volatile("ldmatrix.sync.aligned.m8n8.x4.shared.b16 {%0,%1,%2,%3}, [%4];"
                 : "=r"(r[0]), "=r"(r[1]), "=r"(r[2]), "=r"(r[3]) : "r"(addr));
}
__device__ __forceinline__ void mma_bf16(float* d, const uint32_t* a, uint32_t b0, uint32_t b1) {
    asm volatile(
        "mma.sync.aligned.m16n8k16.row.col.f32.bf16.bf16.f32 "
        "{%0,%1,%2,%3}, {%4,%5,%6,%7}, {%8,%9}, {%0,%1,%2,%3};"
        : "+f"(d[0]), "+f"(d[1]), "+f"(d[2]), "+f"(d[3])
        : "r"(a[0]), "r"(a[1]), "r"(a[2]), "r"(a[3]), "r"(b0), "r"(b1));
}

// ---------------- prep: bf16 hi/lo splits ----------------
__global__ void k_prep_w(const float* __restrict__ Wq, const float* __restrict__ Wkv,
                         const float* __restrict__ Wp) {
    int row = blockIdx.x, t = threadIdx.x;
    if (row < 768) {
        float v = (row < 256) ? Wq[row * 256 + t] : Wkv[(row - 256) * 256 + t];
        __nv_bfloat16 hi = __float2bfloat16(v);
        g_wh[row * 256 + t] = hi;
        g_wl[row * 256 + t] = __float2bfloat16(v - __bfloat162float(hi));
    } else {
        int r = row - 768;
        float v = Wp[r * 256 + t];
        __nv_bfloat16 hi = __float2bfloat16(v);
        g_pwh[r * 256 + t] = hi;
        g_pwl[r * 256 + t] = __float2bfloat16(v - __bfloat162float(hi));
    }
}

__global__ void k_xsplit(const float* __restrict__ x) {
    __shared__ float tile[32][33];
    int tx = threadIdx.x, ty = threadIdx.y;  // 32x8
    int n0 = blockIdx.x * 32, c0 = blockIdx.y * 32, b = blockIdx.z;
#pragma unroll
    for (int yy = 0; yy < 32; yy += 8)
        tile[ty + yy][tx] = x[((size_t)b * 256 + c0 + ty + yy) * 4096 + n0 + tx];
    __syncthreads();
#pragma unroll
    for (int yy = 0; yy < 32; yy += 8) {
        int nl = ty + yy;
        float v = tile[tx][nl];
        __nv_bfloat16 hi = __float2bfloat16(v);
        size_t o = ((size_t)b * 4096 + n0 + nl) * 256 + c0 + tx;
        g_xh[o] = hi;
        g_xl[o] = __float2bfloat16(v - __bfloat162float(hi));
    }
}

__global__ void k_osplit() {
    size_t i = (size_t)blockIdx.x * 256 + threadIdx.x;
    float v = g_o[i];
    __nv_bfloat16 hi = __float2bfloat16(v);
    g_oh[i] = hi;
    g_ol[i] = __float2bfloat16(v - __bfloat162float(hi));
}

// ---------------- tensor-core GEMM via mma.sync (bf16 hi/lo 3-MMA split) ----------------
// C[128 n-rows][j] = A[128][256] @ W[j][256]^T, looping JT j-tiles of 64.
// MODE 0: A = g_xh/g_xl, W = g_wh/g_wl (768 rows) -> g_q/g_k/g_v row-major [b][n][256]
// MODE 1: A = g_oh/g_ol, W = g_pwh/g_pwl (256 rows) -> transposed out[b][j][n] + bias
template <int JT, int MODE>
__global__ __launch_bounds__(256, 1)
void k_gemm_mma(const float* __restrict__ bias, float* __restrict__ outp) {
    extern __shared__ __align__(16) char dsm[];
    __nv_bfloat16* sAh = (__nv_bfloat16*)dsm;
    __nv_bfloat16* sAl = (__nv_bfloat16*)(dsm + A_BYTES);
    __nv_bfloat16* sBh = (__nv_bfloat16*)(dsm + 2 * A_BYTES);
    __nv_bfloat16* sBl = (__nv_bfloat16*)(dsm + 2 * A_BYTES + B_BYTES);
    float* stag = (float*)(dsm + 2 * A_BYTES);  // epilogue staging aliases B (dead then)

    const int t = threadIdx.x;
    const int lane = t & 31, wid = t >> 5;
    const int wm = wid & 3, wn = wid >> 2;       // warp tile: 32(m) x 32(n)
    const int b = blockIdx.y, n0 = blockIdx.x * 128;

    // ---- load resident A tile (hi+lo) ----
    const __nv_bfloat16* Agh = (MODE == 0 ? g_xh : g_oh) + ((size_t)b * 4096 + n0) * 256;
    const __nv_bfloat16* Agl = (MODE == 0 ? g_xl : g_ol) + ((size_t)b * 4096 + n0) * 256;
#pragma unroll
    for (int it = 0; it < 16; it++) {
        int idx = t + it * 256;                 // 4096 chunks of 8 bf16
        int r = idx >> 5, ch = idx & 31;
        *(uint4*)&sAh[r * AP + ch * 8] = *(const uint4*)(Agh + (size_t)r * 256 + ch * 8);
        *(uint4*)&sAl[r * AP + ch * 8] = *(const uint4*)(Agl + (size_t)r * 256 + ch * 8);
    }

    // ---- per-thread ldmatrix byte offsets ----
    const int q8 = lane >> 3, r8 = lane & 7;
    // A quadrants: reg order (m0-7,k0) (m8-15,k0) (m0-7,k8) (m8-15,k8)
    uint32_t aoff[2], boff[2];
#pragma unroll
    for (int mt = 0; mt < 2; mt++) {
        int row = wm * 32 + mt * 16 + (q8 & 1) * 8 + r8;
        aoff[mt] = (uint32_t)((row * AP + (q8 >> 1) * 8) * 2);
    }
    // B quadrants: (n0-7,k0) (n0-7,k8) (n8-15,k0) (n8-15,k8)
#pragma unroll
    for (int p = 0; p < 2; p++) {
        int nrow = wn * 32 + p * 16 + (q8 >> 1) * 8 + r8;
        boff[p] = (uint32_t)((nrow * AP + (q8 & 1) * 8) * 2);
    }
    const uint32_t uAh = smem_u32(sAh), uAl = smem_u32(sAl);
    const uint32_t uBh = smem_u32(sBh), uBl = smem_u32(sBl);

    for (int jt = 0; jt < JT; jt++) {
        // ---- load B tile (64 weight rows, hi+lo) ----
        const __nv_bfloat16* Wgh = (MODE == 0 ? g_wh : g_pwh) + (size_t)(jt * 64) * 256;
        const __nv_bfloat16* Wgl = (MODE == 0 ? g_wl : g_pwl) + (size_t)(jt * 64) * 256;
#pragma unroll
        for (int it = 0; it < 8; it++) {
            int idx = t + it * 256;             // 2048 chunks
            int r = idx >> 5, ch = idx & 31;
            *(uint4*)&sBh[r * AP + ch * 8] = *(const uint4*)(Wgh + (size_t)r * 256 + ch * 8);
            *(uint4*)&sBl[r * AP + ch * 8] = *(const uint4*)(Wgl + (size_t)r * 256 + ch * 8);
        }
        __syncthreads();

        float acc[2][4][4];
#pragma unroll
        for (int mt = 0; mt < 2; mt++)
#pragma unroll
            for (int nt = 0; nt < 4; nt++)
#pragma unroll
                for (int e = 0; e < 4; e++) acc[mt][nt][e] = 0.f;

#pragma unroll 4
        for (int ks = 0; ks < 16; ks++) {
            uint32_t ko = (uint32_t)(ks * 32);  // 16 k-elems = 32 bytes
            uint32_t A_h[2][4], A_l[2][4], B_h[2][4], B_l[2][4];
            ldm_x4(A_h[0], uAh + aoff[0] + ko);
            ldm_x4(A_h[1], uAh + aoff[1] + ko);
            ldm_x4(A_l[0], uAl + aoff[0] + ko);
            ldm_x4(A_l[1], uAl + aoff[1] + ko);
            ldm_x4(B_h[0], uBh + boff[0] + ko);
            ldm_x4(B_h[1], uBh + boff[1] + ko);
            ldm_x4(B_l[0], uBl + boff[0] + ko);
            ldm_x4(B_l[1], uBl + boff[1] + ko);
#pragma unroll
            for (int mt = 0; mt < 2; mt++) {
#pragma unroll
                for (int nt = 0; nt < 4; nt++) {
                    int p = nt >> 1, hf = (nt & 1) * 2;
                    mma_bf16(acc[mt][nt], A_h[mt], B_h[p][hf], B_h[p][hf + 1]);
                    mma_bf16(acc[mt][nt], A_h[mt], B_l[p][hf], B_l[p][hf + 1]);
                    mma_bf16(acc[mt][nt], A_l[mt], B_h[p][hf], B_h[p][hf + 1]);
                }
            }
        }
        __syncthreads();   // B dead; staging region safe to write

        // ---- stage fragments to smem [128][68] ----
        {
            int r0 = lane >> 2, c0 = (lane & 3) * 2;
#pragma unroll
            for (int mt = 0; mt < 2; mt++) {
#pragma unroll
                for (int nt = 0; nt < 4; nt++) {
                    int row = wm * 32 + mt * 16 + r0;
                    int col = wn * 32 + nt * 8 + c0;
                    stag[row * 68 + col]           = acc[mt][nt][0];
                    stag[row * 68 + col + 1]       = acc[mt][nt][1];
                    stag[(row + 8) * 68 + col]     = acc[mt][nt][2];
                    stag[(row + 8) * 68 + col + 1] = acc[mt][nt][3];
                }
            }
        }
        __syncthreads();

        // ---- coalesced stores ----
        if (MODE == 0) {
            float* dst = (jt < 4) ? g_q : (jt < 8) ? g_k : g_v;
            int jl = (jt & 3) * 64;
#pragma unroll
            for (int it = 0; it < 8; it++) {
                int idx = t + it * 256;          // 2048 float4
                int m = idx >> 4, j4 = (idx & 15) * 4;
                *(float4*)&dst[((size_t)b * 4096 + n0 + m) * 256 + jl + j4] =
                    *(float4*)&stag[m * 68 + j4];
            }
        } else {
            int m = t & 127, j0 = t >> 7;
#pragma unroll 8
            for (int j = j0; j < 64; j += 2) {
                float v = stag[m * 68 + j] + bias[jt * 64 + j];
                outp[((size_t)b * 256 + jt * 64 + j) * 4096 + n0 + m] = v;
            }
        }
        __syncthreads();   // staging reused / B reloaded next iteration
    }
}

// ---------------- bilinear coeffs for 7 -> 64 resize ----------------
__device__ __forceinline__ void lin7(int i, int& j0, int& j1, float& w) {
    float c = (i + 0.5f) * (7.0f / 64.0f) - 0.5f;
    float f = floorf(c);
    w = c - f;
    int j = (int)f;
    j0 = max(0, min(6, j));
    j1 = max(0, min(6, j + 1));
}

__device__ __forceinline__ float bil7(const float* img, int y0, int y1, float wy,
                                      int x0, int x1, float wx) {
    float v0 = img[y0 * 7 + x0] * (1.f - wx) + img[y0 * 7 + x1] * wx;
    float v1 = img[y1 * 7 + x0] * (1.f - wx) + img[y1 * 7 + x1] * wx;
    return v0 * (1.f - wy) + v1 * wy;
}

// ---------------- K1: position biases ----------------
__global__ void k_bias(const float* __restrict__ an, const float* __restrict__ na,
                       const float* __restrict__ ahb, const float* __restrict__ awb,
                       const float* __restrict__ hab, const float* __restrict__ wab) {
    int n = blockIdx.x * 256 + threadIdx.x;
    int a = blockIdx.y, h = blockIdx.z;
    int y = n >> 6, x = n & 63;
    int y0, y1, x0, x1; float wy, wx;
    lin7(y, y0, y1, wy);
    lin7(x, x0, x1, wx);
    const float* i1 = an + (h * AG + a) * 49;
    const float* i2 = na + (h * AG + a) * 49;
    float v1 = bil7(i1, y0, y1, wy, x0, x1, wx);
    float v2 = bil7(i2, y0, y1, wy, x0, x1, wx);
    g_bias1[(h * AG + a) * Nn + n] = v1 + ahb[(h * AG + a) * 64 + y] + awb[(h * AG + a) * 64 + x];
    g_bias2[(h * Nn + n) * AG + a] = v2 + hab[(h * 64 + y) * AG + a] + wab[(h * 64 + x) * AG + a];
}

// ---------------- K3: adaptive avg pool q -> agent ----------------
__global__ void k_pool() {
    int c = threadIdx.x;
    int a = blockIdx.x;
    int b = blockIdx.y;
    int p = a / 7, q = a % 7;
    int ys = (p * 64) / 7, ye = ((p + 1) * 64 + 6) / 7;
    int xs = (q * 64) / 7, xe = ((q + 1) * 64 + 6) / 7;
    float s = 0.f;
    for (int y = ys; y < ye; y++)
        for (int x = xs; x < xe; x++)
            s += g_q[(b * Nn + y * 64 + x) * Cc + c];
    g_agent[(b * AG + a) * Cc + c] = s * (1.0f / ((ye - ys) * (xe - xs)));
}

// ---------------- K4: stage-1 scores ----------------
__global__ __launch_bounds__(256) void k_s1() {
    __shared__ __align__(16) float ah_s[AG * HD];
    __shared__ __align__(16) float k_s[128][33];
    int t = threadIdx.x;
    int n0 = blockIdx.x * 128, h = blockIdx.y, b = blockIdx.z;
    for (int idx = t; idx < AG * HD; idx += 256) {
        int a = idx >> 5, d = idx & 31;
        ah_s[idx] = g_agent[(b * AG + a) * Cc + h * HD + d];
    }
#pragma unroll
    for (int i = 0; i < 16; i++) {
        int idx = t + i * 256;
        int nn = idx >> 5, d = idx & 31;
        k_s[nn][d] = g_k[(b * Nn + n0 + nn) * Cc + h * HD + d];
    }
    __syncthreads();
    int n_l = t & 127;
    int a0 = t >> 7;
    float kreg[32];
#pragma unroll
    for (int d = 0; d < 32; d++) kreg[d] = k_s[n_l][d];
    float* Srow = g_S + ((b * NH + h) * AG) * Nn;
    const float* brow = g_bias1 + (h * AG) * Nn;
    for (int a = a0; a < AG; a += 2) {
        float s = 0.f;
#pragma unroll
        for (int i = 0; i < 8; i++) {
            float4 w = *(const float4*)&ah_s[a * HD + i * 4];
            s += w.x * kreg[i * 4 + 0] + w.y * kreg[i * 4 + 1]
               + w.z * kreg[i * 4 + 2] + w.w * kreg[i * 4 + 3];
        }
        Srow[a * Nn + n0 + n_l] = s * SCALE + brow[a * Nn + n0 + n_l];
    }
}

// ---------------- K5: per-row max / sum-exp ----------------
__global__ void k_stats() {
    int a = blockIdx.x, h = blockIdx.y, b = blockIdx.z;
    const float* row = g_S + ((b * NH + h) * AG + a) * Nn;
    int t = threadIdx.x;
    __shared__ float red[256];
    float mx = -1e30f;
    for (int i = t; i < Nn; i += 256) mx = fmaxf(mx, row[i]);
    red[t] = mx;
    __syncthreads();
    for (int s = 128; s > 0; s >>= 1) {
        if (t < s) red[t] = fmaxf(red[t], red[t + s]);
        __syncthreads();
    }
    mx = red[0];
    __syncthreads();
    float sm = 0.f;
    for (int i = t; i < Nn; i += 256) sm += __expf(row[i] - mx);
    red[t] = sm;
    __syncthreads();
    for (int s = 128; s > 0; s >>= 1) {
        if (t < s) red[t] += red[t + s];
        __syncthreads();
    }
    if (t == 0) {
        int idx = (b * NH + h) * AG + a;
        g_m[idx] = mx;
        g_l[idx] = red[0];
    }
}

// ---------------- K6: agent_v = softmax(S) @ V ----------------
__global__ __launch_bounds__(256) void k_av() {
    __shared__ __align__(16) float p_s[AG][68];
    __shared__ __align__(16) float v_s[HD][68];
    __shared__ float mx_s[AG], li_s[AG];
    int h = blockIdx.x, b = blockIdx.y;
    int t = threadIdx.x;
    int bh = b * NH + h;
    if (t < AG) {
        mx_s[t] = g_m[bh * AG + t];
        li_s[t] = 1.0f / g_l[bh * AG + t];
    }
    __syncthreads();
    int d2 = t & 15;
    int grp = t >> 4;
    float acc[4][2];
#pragma unroll
    for (int i = 0; i < 4; i++) { acc[i][0] = 0.f; acc[i][1] = 0.f; }
    const float* Sbase = g_S + bh * AG * Nn;
    const float* vbase = g_v + b * Nn * Cc + h * HD;
    for (int n0 = 0; n0 < Nn; n0 += 64) {
#pragma unroll
        for (int i = 0; i < 8; i++) {
            int idx = t + i * 256;
            int nn = idx >> 5, d = idx & 31;
            v_s[d][nn] = vbase[(n0 + nn) * Cc + d];
        }
        for (int idx = t; idx < AG * 64; idx += 256) {
            int a = idx >> 6, nn = idx & 63;
            float s = Sbase[a * Nn + n0 + nn];
            p_s[a][nn] = __expf(s - mx_s[a]) * li_s[a];
        }
        __syncthreads();
#pragma unroll
        for (int i = 0; i < 4; i++) {
            int a = grp + i * 16;
            if (a < AG) {
#pragma unroll
                for (int n4 = 0; n4 < 64; n4 += 4) {
                    float4 p4 = *(const float4*)&p_s[a][n4];
                    float4 va = *(const float4*)&v_s[d2][n4];
                    float4 vb = *(const float4*)&v_s[d2 + 16][n4];
                    acc[i][0] += p4.x * va.x + p4.y * va.y + p4.z * va.z + p4.w * va.w;
                    acc[i][1] += p4.x * vb.x + p4.y * vb.y + p4.z * vb.z + p4.w * vb.w;
                }
            }
        }
        __syncthreads();
    }
#pragma unroll
    for (int i = 0; i < 4; i++) {
        int a = grp + i * 16;
        if (a < AG) {
            g_agentv[(bh * AG + a) * HD + d2]      = acc[i][0];
            g_agentv[(bh * AG + a) * HD + d2 + 16] = acc[i][1];
        }
    }
}

// ---------------- K7: fused stage-2 ----------------
__global__ __launch_bounds__(256) void k_st2() {
    __shared__ __align__(16) float ah_s[AG * HD];
    __shared__ __align__(16) float av_s[AG * HD];
    __shared__ __align__(16) float p_sm[AG][128];
    __shared__ float li_sm[128];
    int t = threadIdx.x;
    int n0 = blockIdx.x * 128, h = blockIdx.y, b = blockIdx.z;
    for (int idx = t; idx < AG * HD; idx += 256) {
        int a = idx >> 5, d = idx & 31;
        ah_s[idx] = g_agent[(b * AG + a) * Cc + h * HD + d];
        av_s[idx] = g_agentv[((b * NH + h) * AG + a) * HD + d];
    }
    __syncthreads();
    {
        int n_l = t & 127, a0 = t >> 7;
        float4 q4[8];
        const float4* qp = (const float4*)(g_q + (b * Nn + n0 + n_l) * Cc + h * HD);
#pragma unroll
        for (int i = 0; i < 8; i++) q4[i] = qp[i];
        const float* b2 = g_bias2 + (h * Nn + n0 + n_l) * AG;
        for (int a = a0; a < AG; a += 2) {
            float s = 0.f;
#pragma unroll
            for (int i = 0; i < 8; i++) {
                float4 w = *(const float4*)&ah_s[a * HD + i * 4];
                s += q4[i].x * w.x + q4[i].y * w.y + q4[i].z * w.z + q4[i].w * w.w;
            }
            p_sm[a][n_l] = s * SCALE + b2[a];
        }
    }
    __syncthreads();
    if (t < 128) {
        float mx = -1e30f;
        for (int a = 0; a < AG; a++) mx = fmaxf(mx, p_sm[a][t]);
        float sm = 0.f;
        for (int a = 0; a < AG; a++) {
            float e = __expf(p_sm[a][t] - mx);
            p_sm[a][t] = e;
            sm += e;
        }
        li_sm[t] = 1.0f / sm;
    }
    __syncthreads();
    {
        int d = t & 31, grp = t >> 5;
        int nb = grp * 16;
        float acc[16];
#pragma unroll
        for (int i = 0; i < 16; i++) acc[i] = 0.f;
        for (int a = 0; a < AG; a++) {
            float av = av_s[a * HD + d];
#pragma unroll
            for (int i4 = 0; i4 < 4; i4++) {
                float4 p4 = *(const float4*)&p_sm[a][nb + i4 * 4];
                acc[i4 * 4 + 0] += p4.x * av;
                acc[i4 * 4 + 1] += p4.y * av;
                acc[i4 * 4 + 2] += p4.z * av;
                acc[i4 * 4 + 3] += p4.w * av;
            }
        }
#pragma unroll
        for (int i = 0; i < 16; i++) {
            int n = nb + i;
            g_o[(b * Nn + n0 + n) * Cc + h * HD + d] = acc[i] * li_sm[n];
        }
    }
}

// ---------------- K8: depthwise 3x3 conv, accumulate into g_o ----------------
__global__ void k_dw(const float* __restrict__ Wd, const float* __restrict__ bd) {
    int c = threadIdx.x;
    int n = blockIdx.x, b = blockIdx.y;
    int y = n >> 6, x = n & 63;
    float s = bd[c];
#pragma unroll
    for (int dy = -1; dy <= 1; dy++) {
        int yy = y + dy;
        if (yy < 0 || yy > 63) continue;
#pragma unroll
        for (int dx = -1; dx <= 1; dx++) {
            int xx = x + dx;
            if (xx < 0 || xx > 63) continue;
            s += g_v[(b * Nn + yy * 64 + xx) * Cc + c] * Wd[c * 9 + (dy + 1) * 3 + (dx + 1)];
        }
    }
    g_o[(b * Nn + n) * Cc + c] += s;
}

// ---------------- launch ----------------
extern "C" void kernel_launch(void* const* d_in, const int* in_sizes, int n_in,
                              void* d_out, int out_size) {
    const float* x     = (const float*)d_in[0];
    const float* Wq    = (const float*)d_in[1];
    const float* Wkv   = (const float*)d_in[2];
    const float* Wproj = (const float*)d_in[3];
    const float* bproj = (const float*)d_in[4];
    const float* Wdwc  = (const float*)d_in[5];
    const float* bdwc  = (const float*)d_in[6];
    const float* an    = (const float*)d_in[7];
    const float* na    = (const float*)d_in[8];
    const float* ahb   = (const float*)d_in[9];
    const float* awb   = (const float*)d_in[10];
    const float* hab   = (const float*)d_in[11];
    const float* wab   = (const float*)d_in[12];
    float* out = (float*)d_out;

    cudaFuncSetAttribute(k_gemm_mma<12, 0>, cudaFuncAttributeMaxDynamicSharedMemorySize, SMEM_DYN);
    cudaFuncSetAttribute(k_gemm_mma<4, 1>,  cudaFuncAttributeMaxDynamicSharedMemorySize, SMEM_DYN);

    k_bias   <<<dim3(Nn / 256, AG, NH), 256>>>(an, na, ahb, awb, hab, wab);
    k_prep_w <<<1024, 256>>>(Wq, Wkv, Wproj);
    k_xsplit <<<dim3(128, 8, Bb), dim3(32, 8)>>>(x);
    k_gemm_mma<12, 0><<<dim3(32, Bb), 256, SMEM_DYN>>>(nullptr, nullptr);
    k_pool   <<<dim3(AG, Bb), 256>>>();
    k_s1     <<<dim3(Nn / 128, NH, Bb), 256>>>();
    k_stats  <<<dim3(AG, NH, Bb), 256>>>();
    k_av     <<<dim3(NH, Bb), 256>>>();
    k_st2    <<<dim3(Nn / 128, NH, Bb), 256>>>();
    k_dw     <<<dim3(Nn, Bb), 256>>>(Wdwc, bdwc);
    k_osplit <<<Bb * Nn * Cc / 256, 256>>>();
    k_gemm_mma<4, 1><<<dim3(32, Bb), 256, SMEM_DYN>>>(bproj, out);
}